// round 1
// baseline (speedup 1.0000x reference)
#include <cuda_runtime.h>
#include <cuda_bf16.h>
#include <cstdint>

#define NN 50000
#define EE 800000
#define LN_EPS 1e-5f

// ---------------- static scratch (no allocations allowed) ----------------
__device__ int   g_deg[NN];
__device__ int   g_rowptr[NN + 1];
__device__ int   g_cursor[NN];
__device__ int   g_csrsrc[EE];
__device__ float g_invdeg[NN];
__device__ float g_agg0[(size_t)NN * 64];   // aggregation of x (shared by both towers)
__device__ float g_bufA[(size_t)NN * 128];  // h0
__device__ float g_bufB[(size_t)NN * 128];  // agg scratch
__device__ float g_bufC[(size_t)NN * 128];  // h1

// ---------------- degree count ----------------
__global__ void k_count(const int* __restrict__ dst, int* __restrict__ deg) {
    int e = blockIdx.x * blockDim.x + threadIdx.x;
    if (e < EE) atomicAdd(&deg[dst[e]], 1);
}

// ---------------- single-block exclusive scan over N=50000 ----------------
__global__ void k_scan(const int* __restrict__ deg, int* __restrict__ rowptr,
                       int* __restrict__ cursor) {
    __shared__ int sums[1024];
    const int t = threadIdx.x;
    const int CH = (NN + 1023) / 1024;  // 49
    int s = 0;
    #pragma unroll 4
    for (int i = 0; i < CH; ++i) {
        int idx = t * CH + i;
        if (idx < NN) s += deg[idx];
    }
    sums[t] = s;
    __syncthreads();
    for (int off = 1; off < 1024; off <<= 1) {
        int v = 0;
        if (t >= off) v = sums[t - off];
        __syncthreads();
        if (t >= off) sums[t] += v;
        __syncthreads();
    }
    int run = (t == 0) ? 0 : sums[t - 1];
    for (int i = 0; i < CH; ++i) {
        int idx = t * CH + i;
        if (idx < NN) {
            rowptr[idx] = run;
            cursor[idx] = run;
            run += deg[idx];
        }
    }
    if (t == 1023) rowptr[NN] = run;  // = E
}

__global__ void k_invdeg(const int* __restrict__ deg, float* __restrict__ invdeg) {
    int n = blockIdx.x * blockDim.x + threadIdx.x;
    if (n < NN) {
        int d = deg[n];
        invdeg[n] = 1.0f / (float)(d > 0 ? d : 1);
    }
}

__global__ void k_scatter(const int* __restrict__ src, const int* __restrict__ dst,
                          int* __restrict__ cursor, int* __restrict__ csrsrc) {
    int e = blockIdx.x * blockDim.x + threadIdx.x;
    if (e < EE) {
        int pos = atomicAdd(&cursor[dst[e]], 1);
        csrsrc[pos] = src[e];
    }
}

// ---------------- gather-based mean aggregation (warp per node) ----------------
template <int D>
__global__ void k_gather(const float* __restrict__ h, float* __restrict__ out,
                         const int* __restrict__ rowptr, const int* __restrict__ csrsrc,
                         const float* __restrict__ invdeg) {
    int gw   = (blockIdx.x * blockDim.x + threadIdx.x) >> 5;
    int lane = threadIdx.x & 31;
    if (gw >= NN) return;
    int s = rowptr[gw], e = rowptr[gw + 1];
    if (D == 128) {
        float4 a0 = make_float4(0, 0, 0, 0), a1 = make_float4(0, 0, 0, 0);
        int j = s;
        for (; j + 1 < e; j += 2) {
            int s0 = csrsrc[j], s1 = csrsrc[j + 1];
            float4 v0 = *(const float4*)(h + (size_t)s0 * 128 + lane * 4);
            float4 v1 = *(const float4*)(h + (size_t)s1 * 128 + lane * 4);
            a0.x += v0.x; a0.y += v0.y; a0.z += v0.z; a0.w += v0.w;
            a1.x += v1.x; a1.y += v1.y; a1.z += v1.z; a1.w += v1.w;
        }
        if (j < e) {
            int s0 = csrsrc[j];
            float4 v0 = *(const float4*)(h + (size_t)s0 * 128 + lane * 4);
            a0.x += v0.x; a0.y += v0.y; a0.z += v0.z; a0.w += v0.w;
        }
        float iv = invdeg[gw];
        float4 r;
        r.x = (a0.x + a1.x) * iv; r.y = (a0.y + a1.y) * iv;
        r.z = (a0.z + a1.z) * iv; r.w = (a0.w + a1.w) * iv;
        *(float4*)(out + (size_t)gw * 128 + lane * 4) = r;
    } else {  // D == 64
        float2 a0 = make_float2(0, 0), a1 = make_float2(0, 0);
        int j = s;
        for (; j + 1 < e; j += 2) {
            int s0 = csrsrc[j], s1 = csrsrc[j + 1];
            float2 v0 = *(const float2*)(h + (size_t)s0 * 64 + lane * 2);
            float2 v1 = *(const float2*)(h + (size_t)s1 * 64 + lane * 2);
            a0.x += v0.x; a0.y += v0.y;
            a1.x += v1.x; a1.y += v1.y;
        }
        if (j < e) {
            int s0 = csrsrc[j];
            float2 v0 = *(const float2*)(h + (size_t)s0 * 64 + lane * 2);
            a0.x += v0.x; a0.y += v0.y;
        }
        float iv = invdeg[gw];
        float2 r;
        r.x = (a0.x + a1.x) * iv; r.y = (a0.y + a1.y) * iv;
        *(float2*)(out + (size_t)gw * 64 + lane * 2) = r;
    }
}

// ---------------- fused SAGE dense: out = Agg@Wl^T + bl + Hin@Wr^T ----------------
// Virtual K = 2*DI: first DI columns from (Agg, Wl), second DI from (Hin, Wr).
// BM=128, BN=DO, BK=32, 256 threads, 8 x (DO/16) microtile (strided layout).
template <int DI, int DO>
__global__ __launch_bounds__(256) void k_dense(
    const float* __restrict__ Agg, const float* __restrict__ Hin,
    const float* __restrict__ Wl, const float* __restrict__ Wr,
    const float* __restrict__ bl, float* __restrict__ out) {
    constexpr int TN = DO / 16;
    __shared__ float As[32][128 + 4];
    __shared__ float Ws[32][DO + 4];

    const int tid = threadIdx.x;
    const int tx = tid & 15, ty = tid >> 4;
    const int bm = blockIdx.x * 128;

    float acc[8][TN];
    #pragma unroll
    for (int i = 0; i < 8; ++i)
        #pragma unroll
        for (int j = 0; j < TN; ++j) acc[i][j] = 0.f;

    for (int kc = 0; kc < 2 * DI; kc += 32) {
        const float* Ap;
        const float* Wp;
        int kl;
        if (kc < DI) { Ap = Agg; Wp = Wl; kl = kc; }
        else         { Ap = Hin; Wp = Wr; kl = kc - DI; }

        // A tile: 128 rows x 32 cols (transposed store)
        {
            const int c4 = tid & 7, r0 = tid >> 3;
            #pragma unroll
            for (int it = 0; it < 4; ++it) {
                int r = r0 + it * 32;
                int m = bm + r;
                float4 v = make_float4(0, 0, 0, 0);
                if (m < NN) v = *(const float4*)(Ap + (size_t)m * DI + kl + c4 * 4);
                As[c4 * 4 + 0][r] = v.x; As[c4 * 4 + 1][r] = v.y;
                As[c4 * 4 + 2][r] = v.z; As[c4 * 4 + 3][r] = v.w;
            }
        }
        // W tile: DO rows x 32 cols (transposed store)
        {
            const int c4 = tid & 7, o0 = tid >> 3;
            #pragma unroll
            for (int it = 0; it < DO / 32; ++it) {
                int o = o0 + it * 32;
                float4 v = *(const float4*)(Wp + (size_t)o * DI + kl + c4 * 4);
                Ws[c4 * 4 + 0][o] = v.x; Ws[c4 * 4 + 1][o] = v.y;
                Ws[c4 * 4 + 2][o] = v.z; Ws[c4 * 4 + 3][o] = v.w;
            }
        }
        __syncthreads();

        #pragma unroll
        for (int k = 0; k < 32; ++k) {
            float a[8], b[TN];
            #pragma unroll
            for (int i = 0; i < 8; ++i) a[i] = As[k][i * 16 + ty];
            #pragma unroll
            for (int j = 0; j < TN; ++j) b[j] = Ws[k][j * 16 + tx];
            #pragma unroll
            for (int i = 0; i < 8; ++i)
                #pragma unroll
                for (int j = 0; j < TN; ++j) acc[i][j] += a[i] * b[j];
        }
        __syncthreads();
    }

    // epilogue: + bias, store
    float bb[TN];
    #pragma unroll
    for (int j = 0; j < TN; ++j) bb[j] = bl[j * 16 + tx];
    #pragma unroll
    for (int i = 0; i < 8; ++i) {
        int m = bm + i * 16 + ty;
        if (m < NN) {
            #pragma unroll
            for (int j = 0; j < TN; ++j)
                out[(size_t)m * DO + j * 16 + tx] = acc[i][j] + bb[j];
        }
    }
}

// ---------------- LayerNorm + ReLU, warp per node, D=128 ----------------
__global__ void k_lnrelu(float* __restrict__ h, const float* __restrict__ g,
                         const float* __restrict__ b) {
    int n    = (blockIdx.x * blockDim.x + threadIdx.x) >> 5;
    int lane = threadIdx.x & 31;
    if (n >= NN) return;
    float4 v = *(const float4*)(h + (size_t)n * 128 + lane * 4);
    float s = v.x + v.y + v.z + v.w;
    #pragma unroll
    for (int off = 16; off > 0; off >>= 1) s += __shfl_xor_sync(0xFFFFFFFF, s, off);
    float mean = s * (1.0f / 128.0f);
    float dx = v.x - mean, dy = v.y - mean, dz = v.z - mean, dw = v.w - mean;
    float sq = dx * dx + dy * dy + dz * dz + dw * dw;
    #pragma unroll
    for (int off = 16; off > 0; off >>= 1) sq += __shfl_xor_sync(0xFFFFFFFF, sq, off);
    float rs = rsqrtf(sq * (1.0f / 128.0f) + LN_EPS);
    float4 gg = *(const float4*)(g + lane * 4);
    float4 bb = *(const float4*)(b + lane * 4);
    float4 r;
    r.x = fmaxf(dx * rs * gg.x + bb.x, 0.f);
    r.y = fmaxf(dy * rs * gg.y + bb.y, 0.f);
    r.z = fmaxf(dz * rs * gg.z + bb.z, 0.f);
    r.w = fmaxf(dw * rs * gg.w + bb.w, 0.f);
    *(float4*)(h + (size_t)n * 128 + lane * 4) = r;
}

// ---------------- host ----------------
extern "C" void kernel_launch(void* const* d_in, const int* in_sizes, int n_in,
                              void* d_out, int out_size) {
    const float* x   = (const float*)d_in[0];
    const int*   ei  = (const int*)d_in[1];
    const int*   src = ei;
    const int*   dst = ei + EE;

    int *pDeg, *pRow, *pCur, *pCsr;
    float *pInv, *pAgg0, *pA, *pB, *pC;
    cudaGetSymbolAddress((void**)&pDeg, g_deg);
    cudaGetSymbolAddress((void**)&pRow, g_rowptr);
    cudaGetSymbolAddress((void**)&pCur, g_cursor);
    cudaGetSymbolAddress((void**)&pCsr, g_csrsrc);
    cudaGetSymbolAddress((void**)&pInv, g_invdeg);
    cudaGetSymbolAddress((void**)&pAgg0, g_agg0);
    cudaGetSymbolAddress((void**)&pA, g_bufA);
    cudaGetSymbolAddress((void**)&pB, g_bufB);
    cudaGetSymbolAddress((void**)&pC, g_bufC);

    const int EB = (EE + 255) / 256;
    const int NB = (NN + 255) / 256;
    const int GW = (NN * 32 + 255) / 256;   // warp-per-node grids
    const int DB = (NN + 127) / 128;        // dense grid

    cudaMemsetAsync(pDeg, 0, NN * sizeof(int), 0);
    k_count<<<EB, 256>>>(dst, pDeg);
    k_scan<<<1, 1024>>>(pDeg, pRow, pCur);
    k_invdeg<<<NB, 256>>>(pDeg, pInv);
    k_scatter<<<EB, 256>>>(src, dst, pCur, pCsr);

    // shared aggregation of input features
    k_gather<64><<<GW, 256>>>(x, pAgg0, pRow, pCsr, pInv);

    for (int t = 0; t < 2; ++t) {
        const int o = 2 + t * 13;
        const float* Wl0 = (const float*)d_in[o + 0];
        const float* bl0 = (const float*)d_in[o + 1];
        const float* Wr0 = (const float*)d_in[o + 2];
        const float* g0  = (const float*)d_in[o + 3];
        const float* b0  = (const float*)d_in[o + 4];
        const float* Wl1 = (const float*)d_in[o + 5];
        const float* bl1 = (const float*)d_in[o + 6];
        const float* Wr1 = (const float*)d_in[o + 7];
        const float* g1  = (const float*)d_in[o + 8];
        const float* b1  = (const float*)d_in[o + 9];
        const float* Wl2 = (const float*)d_in[o + 10];
        const float* bl2 = (const float*)d_in[o + 11];
        const float* Wr2 = (const float*)d_in[o + 12];
        float* outT = (float*)d_out + (size_t)t * NN * 64;

        // layer 0: x[N,64] -> h0[N,128]
        k_dense<64, 128><<<DB, 256>>>(pAgg0, x, Wl0, Wr0, bl0, pA);
        k_lnrelu<<<GW, 256>>>(pA, g0, b0);
        // layer 1: h0 -> h1[N,128]
        k_gather<128><<<GW, 256>>>(pA, pB, pRow, pCsr, pInv);
        k_dense<128, 128><<<DB, 256>>>(pB, pA, Wl1, Wr1, bl1, pC);
        k_lnrelu<<<GW, 256>>>(pC, g1, b1);
        // layer 2: h1 -> out[N,64]
        k_gather<128><<<GW, 256>>>(pC, pB, pRow, pCsr, pInv);
        k_dense<128, 64><<<DB, 256>>>(pB, pC, Wl2, Wr2, bl2, outT);
    }
}

// round 3
// speedup vs baseline: 1.7180x; 1.7180x over previous
#include <cuda_runtime.h>
#include <cuda_bf16.h>
#include <cstdint>

#define NN 50000
#define EE 800000
#define LN_EPS 1e-5f

// ===================== static scratch =====================
__device__ int   g_deg[NN];
__device__ int   g_rowptr[NN + 1];
__device__ int   g_cursor[NN];
__device__ int   g_csrsrc[EE];
__device__ float g_invdeg[NN];
__device__ float g_agg0[(size_t)NN * 64];
__device__ float g_bufA[(size_t)NN * 128];  // h0
__device__ float g_bufB[(size_t)NN * 128];  // agg scratch
__device__ float g_bufC[(size_t)NN * 128];  // h1

__device__ __forceinline__ float to_tf32(float x) {
    uint32_t u;
    asm("cvt.rna.tf32.f32 %0, %1;" : "=r"(u) : "f"(x));
    return __uint_as_float(u);
}

__device__ __forceinline__ void mma_tf32(float& d0, float& d1, float& d2, float& d3,
                                         uint32_t a0, uint32_t a1, uint32_t a2, uint32_t a3,
                                         uint32_t b0, uint32_t b1) {
    asm volatile(
        "mma.sync.aligned.m16n8k8.row.col.f32.tf32.tf32.f32 "
        "{%0,%1,%2,%3}, {%4,%5,%6,%7}, {%8,%9}, {%0,%1,%2,%3};"
        : "+f"(d0), "+f"(d1), "+f"(d2), "+f"(d3)
        : "r"(a0), "r"(a1), "r"(a2), "r"(a3), "r"(b0), "r"(b1));
}

// ===================== CSR build =====================
__global__ void k_count(const int* __restrict__ dst, int* __restrict__ deg) {
    int e = blockIdx.x * blockDim.x + threadIdx.x;
    if (e < EE) atomicAdd(&deg[dst[e]], 1);
}

__global__ void k_scan(const int* __restrict__ deg, int* __restrict__ rowptr,
                       int* __restrict__ cursor) {
    __shared__ int sums[1024];
    const int t = threadIdx.x;
    const int CH = (NN + 1023) / 1024;
    int s = 0;
    #pragma unroll 4
    for (int i = 0; i < CH; ++i) {
        int idx = t * CH + i;
        if (idx < NN) s += deg[idx];
    }
    sums[t] = s;
    __syncthreads();
    for (int off = 1; off < 1024; off <<= 1) {
        int v = 0;
        if (t >= off) v = sums[t - off];
        __syncthreads();
        if (t >= off) sums[t] += v;
        __syncthreads();
    }
    int run = (t == 0) ? 0 : sums[t - 1];
    for (int i = 0; i < CH; ++i) {
        int idx = t * CH + i;
        if (idx < NN) {
            rowptr[idx] = run;
            cursor[idx] = run;
            run += deg[idx];
        }
    }
    if (t == 1023) rowptr[NN] = run;
}

__global__ void k_invdeg(const int* __restrict__ deg, float* __restrict__ invdeg) {
    int n = blockIdx.x * blockDim.x + threadIdx.x;
    if (n < NN) {
        int d = deg[n];
        invdeg[n] = 1.0f / (float)(d > 0 ? d : 1);
    }
}

__global__ void k_scatter(const int* __restrict__ src, const int* __restrict__ dst,
                          int* __restrict__ cursor, int* __restrict__ csrsrc) {
    int e = blockIdx.x * blockDim.x + threadIdx.x;
    if (e < EE) {
        int pos = atomicAdd(&cursor[dst[e]], 1);
        csrsrc[pos] = src[e];
    }
}

// ===================== gather aggregation =====================
template <int D>
__global__ void k_gather(const float* __restrict__ h, float* __restrict__ out,
                         const int* __restrict__ rowptr, const int* __restrict__ csrsrc,
                         const float* __restrict__ invdeg) {
    int gw   = (blockIdx.x * blockDim.x + threadIdx.x) >> 5;
    int lane = threadIdx.x & 31;
    if (gw >= NN) return;
    int s = rowptr[gw], e = rowptr[gw + 1];
    if (D == 128) {
        float4 a0 = make_float4(0, 0, 0, 0), a1 = make_float4(0, 0, 0, 0);
        int j = s;
        for (; j + 1 < e; j += 2) {
            int s0 = csrsrc[j], s1 = csrsrc[j + 1];
            float4 v0 = *(const float4*)(h + (size_t)s0 * 128 + lane * 4);
            float4 v1 = *(const float4*)(h + (size_t)s1 * 128 + lane * 4);
            a0.x += v0.x; a0.y += v0.y; a0.z += v0.z; a0.w += v0.w;
            a1.x += v1.x; a1.y += v1.y; a1.z += v1.z; a1.w += v1.w;
        }
        if (j < e) {
            int s0 = csrsrc[j];
            float4 v0 = *(const float4*)(h + (size_t)s0 * 128 + lane * 4);
            a0.x += v0.x; a0.y += v0.y; a0.z += v0.z; a0.w += v0.w;
        }
        float iv = invdeg[gw];
        float4 r;
        r.x = (a0.x + a1.x) * iv; r.y = (a0.y + a1.y) * iv;
        r.z = (a0.z + a1.z) * iv; r.w = (a0.w + a1.w) * iv;
        *(float4*)(out + (size_t)gw * 128 + lane * 4) = r;
    } else {
        float2 a0 = make_float2(0, 0), a1 = make_float2(0, 0);
        int j = s;
        for (; j + 1 < e; j += 2) {
            int s0 = csrsrc[j], s1 = csrsrc[j + 1];
            float2 v0 = *(const float2*)(h + (size_t)s0 * 64 + lane * 2);
            float2 v1 = *(const float2*)(h + (size_t)s1 * 64 + lane * 2);
            a0.x += v0.x; a0.y += v0.y;
            a1.x += v1.x; a1.y += v1.y;
        }
        if (j < e) {
            int s0 = csrsrc[j];
            float2 v0 = *(const float2*)(h + (size_t)s0 * 64 + lane * 2);
            a0.x += v0.x; a0.y += v0.y;
        }
        float iv = invdeg[gw];
        float2 r;
        r.x = (a0.x + a1.x) * iv; r.y = (a0.y + a1.y) * iv;
        *(float2*)(out + (size_t)gw * 64 + lane * 2) = r;
    }
}

// ===================== tf32 mma.sync fused SAGE dense =====================
// out[m, :DO] = [Agg(m) | Hin(m)] @ [Wl | Wr]^T + bl
// BM=128, BN=DO, virtual K=2*DI. 8 warps in 4x2 grid; warp tile 32 x (DO/2).
// m16n8k8 tf32 fragments loaded from padded smem (stride 36 -> conflict-free).
template <int DI, int DO>
__global__ __launch_bounds__(256) void k_mma(
    const float* __restrict__ Agg, const float* __restrict__ Hin,
    const float* __restrict__ Wl, const float* __restrict__ Wr,
    const float* __restrict__ bl, float* __restrict__ out) {
    constexpr int WN = DO / 2;   // warp tile N
    constexpr int NI = WN / 8;   // 8-col fragments per warp
    constexpr int ST = 36;       // padded smem stride (floats)

    __shared__ float As[128 * ST];
    __shared__ float Ws[DO * ST];

    const int tid    = threadIdx.x;
    const int wid    = tid >> 5;
    const int lane   = tid & 31;
    const int g      = lane >> 2;   // group id (0..7)
    const int tig    = lane & 3;    // thread in group
    const int warp_m = wid >> 1;    // 0..3
    const int warp_n = wid & 1;     // 0..1
    const int bm     = blockIdx.x * 128;

    float acc[2][NI][4];
    #pragma unroll
    for (int mi = 0; mi < 2; ++mi)
        #pragma unroll
        for (int ni = 0; ni < NI; ++ni)
            #pragma unroll
            for (int q = 0; q < 4; ++q) acc[mi][ni][q] = 0.f;

    #pragma unroll
    for (int ph = 0; ph < 2; ++ph) {
        const float* __restrict__ Asrc = ph ? Hin : Agg;
        const float* __restrict__ Wsrc = ph ? Wr : Wl;
        #pragma unroll
        for (int c = 0; c < DI / 32; ++c) {
            const int kl = c * 32;
            // fill A tile: 128 rows x 32 floats
            #pragma unroll
            for (int i = 0; i < 4; ++i) {
                int flat = tid + i * 256;
                int row = flat >> 3, q = flat & 7;
                int m = bm + row;
                float4 v = make_float4(0.f, 0.f, 0.f, 0.f);
                if (m < NN) v = *(const float4*)(Asrc + (size_t)m * DI + kl + q * 4);
                v.x = to_tf32(v.x); v.y = to_tf32(v.y); v.z = to_tf32(v.z); v.w = to_tf32(v.w);
                *(float4*)(As + row * ST + q * 4) = v;
            }
            // fill W tile: DO rows x 32 floats
            #pragma unroll
            for (int i = 0; i < DO / 32; ++i) {
                int flat = tid + i * 256;
                int row = flat >> 3, q = flat & 7;
                float4 v = *(const float4*)(Wsrc + (size_t)row * DI + kl + q * 4);
                v.x = to_tf32(v.x); v.y = to_tf32(v.y); v.z = to_tf32(v.z); v.w = to_tf32(v.w);
                *(float4*)(Ws + row * ST + q * 4) = v;
            }
            __syncthreads();

            #pragma unroll
            for (int kk = 0; kk < 4; ++kk) {
                const int kb = kk * 8;
                uint32_t a[2][4];
                #pragma unroll
                for (int mi = 0; mi < 2; ++mi) {
                    int rb = warp_m * 32 + mi * 16;
                    a[mi][0] = __float_as_uint(As[(rb + g) * ST + kb + tig]);
                    a[mi][1] = __float_as_uint(As[(rb + g + 8) * ST + kb + tig]);
                    a[mi][2] = __float_as_uint(As[(rb + g) * ST + kb + tig + 4]);
                    a[mi][3] = __float_as_uint(As[(rb + g + 8) * ST + kb + tig + 4]);
                }
                #pragma unroll
                for (int ni = 0; ni < NI; ++ni) {
                    int nb = warp_n * WN + ni * 8;
                    uint32_t b0 = __float_as_uint(Ws[(nb + g) * ST + kb + tig]);
                    uint32_t b1 = __float_as_uint(Ws[(nb + g) * ST + kb + tig + 4]);
                    #pragma unroll
                    for (int mi = 0; mi < 2; ++mi)
                        mma_tf32(acc[mi][ni][0], acc[mi][ni][1], acc[mi][ni][2], acc[mi][ni][3],
                                 a[mi][0], a[mi][1], a[mi][2], a[mi][3], b0, b1);
                }
            }
            __syncthreads();
        }
    }

    // epilogue: + bias, store (c0,c1)->(row g, cols 2tig,2tig+1), (c2,c3)->(row g+8)
    #pragma unroll
    for (int ni = 0; ni < NI; ++ni) {
        int col = warp_n * WN + ni * 8 + tig * 2;
        float b0 = bl[col], b1 = bl[col + 1];
        #pragma unroll
        for (int mi = 0; mi < 2; ++mi) {
            int r0 = bm + warp_m * 32 + mi * 16 + g;
            if (r0 < NN) {
                float2 w0 = make_float2(acc[mi][ni][0] + b0, acc[mi][ni][1] + b1);
                *(float2*)(out + (size_t)r0 * DO + col) = w0;
            }
            int r1 = r0 + 8;
            if (r1 < NN) {
                float2 w1 = make_float2(acc[mi][ni][2] + b0, acc[mi][ni][3] + b1);
                *(float2*)(out + (size_t)r1 * DO + col) = w1;
            }
        }
    }
}

// ===================== LayerNorm + ReLU, warp per node, D=128 =====================
__global__ void k_lnrelu(float* __restrict__ h, const float* __restrict__ g,
                         const float* __restrict__ b) {
    int n    = (blockIdx.x * blockDim.x + threadIdx.x) >> 5;
    int lane = threadIdx.x & 31;
    if (n >= NN) return;
    float4 v = *(const float4*)(h + (size_t)n * 128 + lane * 4);
    float s = v.x + v.y + v.z + v.w;
    #pragma unroll
    for (int off = 16; off > 0; off >>= 1) s += __shfl_xor_sync(0xFFFFFFFF, s, off);
    float mean = s * (1.0f / 128.0f);
    float dx = v.x - mean, dy = v.y - mean, dz = v.z - mean, dw = v.w - mean;
    float sq = dx * dx + dy * dy + dz * dz + dw * dw;
    #pragma unroll
    for (int off = 16; off > 0; off >>= 1) sq += __shfl_xor_sync(0xFFFFFFFF, sq, off);
    float rs = rsqrtf(sq * (1.0f / 128.0f) + LN_EPS);
    float4 gg = *(const float4*)(g + lane * 4);
    float4 bb = *(const float4*)(b + lane * 4);
    float4 r;
    r.x = fmaxf(dx * rs * gg.x + bb.x, 0.f);
    r.y = fmaxf(dy * rs * gg.y + bb.y, 0.f);
    r.z = fmaxf(dz * rs * gg.z + bb.z, 0.f);
    r.w = fmaxf(dw * rs * gg.w + bb.w, 0.f);
    *(float4*)(h + (size_t)n * 128 + lane * 4) = r;
}

// ===================== host =====================
extern "C" void kernel_launch(void* const* d_in, const int* in_sizes, int n_in,
                              void* d_out, int out_size) {
    const float* x   = (const float*)d_in[0];
    const int*   ei  = (const int*)d_in[1];
    const int*   src = ei;
    const int*   dst = ei + EE;

    int *pDeg, *pRow, *pCur, *pCsr;
    float *pInv, *pAgg0, *pA, *pB, *pC;
    cudaGetSymbolAddress((void**)&pDeg, g_deg);
    cudaGetSymbolAddress((void**)&pRow, g_rowptr);
    cudaGetSymbolAddress((void**)&pCur, g_cursor);
    cudaGetSymbolAddress((void**)&pCsr, g_csrsrc);
    cudaGetSymbolAddress((void**)&pInv, g_invdeg);
    cudaGetSymbolAddress((void**)&pAgg0, g_agg0);
    cudaGetSymbolAddress((void**)&pA, g_bufA);
    cudaGetSymbolAddress((void**)&pB, g_bufB);
    cudaGetSymbolAddress((void**)&pC, g_bufC);

    const int EB = (EE + 255) / 256;
    const int NB = (NN + 255) / 256;
    const int GW = (NN * 32 + 255) / 256;
    const int DB = (NN + 127) / 128;  // 391 CTAs

    cudaMemsetAsync(pDeg, 0, NN * sizeof(int), 0);
    k_count<<<EB, 256>>>(dst, pDeg);
    k_scan<<<1, 1024>>>(pDeg, pRow, pCur);
    k_invdeg<<<NB, 256>>>(pDeg, pInv);
    k_scatter<<<EB, 256>>>(src, dst, pCur, pCsr);

    // shared aggregation of input features
    k_gather<64><<<GW, 256>>>(x, pAgg0, pRow, pCsr, pInv);

    for (int t = 0; t < 2; ++t) {
        const int o = 2 + t * 13;
        const float* Wl0 = (const float*)d_in[o + 0];
        const float* bl0 = (const float*)d_in[o + 1];
        const float* Wr0 = (const float*)d_in[o + 2];
        const float* g0  = (const float*)d_in[o + 3];
        const float* b0  = (const float*)d_in[o + 4];
        const float* Wl1 = (const float*)d_in[o + 5];
        const float* bl1 = (const float*)d_in[o + 6];
        const float* Wr1 = (const float*)d_in[o + 7];
        const float* g1  = (const float*)d_in[o + 8];
        const float* b1  = (const float*)d_in[o + 9];
        const float* Wl2 = (const float*)d_in[o + 10];
        const float* bl2 = (const float*)d_in[o + 11];
        const float* Wr2 = (const float*)d_in[o + 12];
        float* outT = (float*)d_out + (size_t)t * NN * 64;

        // layer 0: [agg(x) | x] -> h0[N,128]
        k_mma<64, 128><<<DB, 256>>>(pAgg0, x, Wl0, Wr0, bl0, pA);
        k_lnrelu<<<GW, 256>>>(pA, g0, b0);
        // layer 1
        k_gather<128><<<GW, 256>>>(pA, pB, pRow, pCsr, pInv);
        k_mma<128, 128><<<DB, 256>>>(pB, pA, Wl1, Wr1, bl1, pC);
        k_lnrelu<<<GW, 256>>>(pC, g1, b1);
        // layer 2 (no LN)
        k_gather<128><<<GW, 256>>>(pC, pB, pRow, pCsr, pInv);
        k_mma<128, 64><<<DB, 256>>>(pB, pC, Wl2, Wr2, bl2, outT);
    }
}